// round 7
// baseline (speedup 1.0000x reference)
#include <cuda_runtime.h>
#include <cuda_bf16.h>
#include <math.h>
#include <stdint.h>

// Problem dims (fixed)
#define BB 2
#define SS 4096
#define EE 1024
#define HH 16
#define DD 64
#define ROWS (BB*SS)          // 8192

typedef __nv_bfloat16 bf16;
typedef unsigned short ushort_t;

// ---------------- scratch (no allocs allowed) ----------------
__device__ float  g_bq[ROWS*EE];
__device__ float  g_bk[ROWS*EE];
__device__ float  g_bv[ROWS*EE];
__device__ float  g_bg[ROWS*EE];
__device__ float  g_bo[ROWS*EE];
__device__ float4 g_ab4[ROWS*HH];   // (alpha, beta, k.q, unused)

__device__ ushort_t g_xh[ROWS*EE];
__device__ ushort_t g_xl[ROWS*EE];
__device__ ushort_t g_yh[ROWS*EE];
__device__ ushort_t g_yl[ROWS*EE];
__device__ ushort_t g_wq_h[EE*EE], g_wq_l[EE*EE];
__device__ ushort_t g_wk_h[EE*EE], g_wk_l[EE*EE];
__device__ ushort_t g_wv_h[EE*EE], g_wv_l[EE*EE];
__device__ ushort_t g_wg_h[EE*EE], g_wg_l[EE*EE];
__device__ ushort_t g_wo_h[EE*EE], g_wo_l[EE*EE];

__device__ __forceinline__ uint32_t smem_u32(const void* p) {
    uint32_t a;
    asm("{ .reg .u64 t; cvta.to.shared.u64 t, %1; cvt.u32.u64 %0, t; }" : "=r"(a) : "l"(p));
    return a;
}

#define LDSM4(r, addr) \
    asm volatile("ldmatrix.sync.aligned.m8n8.x4.shared.b16 {%0,%1,%2,%3}, [%4];" \
        : "=r"((r)[0]), "=r"((r)[1]), "=r"((r)[2]), "=r"((r)[3]) : "r"(addr))

#define MMA16816(d, a, b0, b1) \
    asm volatile("mma.sync.aligned.m16n8k16.row.col.f32.bf16.bf16.f32 " \
        "{%0,%1,%2,%3},{%4,%5,%6,%7},{%8,%9},{%0,%1,%2,%3};" \
        : "+f"((d)[0]), "+f"((d)[1]), "+f"((d)[2]), "+f"((d)[3]) \
        : "r"((a)[0]), "r"((a)[1]), "r"((a)[2]), "r"((a)[3]), "r"(b0), "r"(b1))

// =============================================================
// split-bf16 GEMM v2 on mma.sync: C[8192,1024] = A @ Bt^T, fp32 acc
//   C = Ah*Bh + Ah*Bl + Al*Bh
// CTA 128x128, 512 thr (16 warps, 2m x 8n), warp tile 64x16.
// BK=16, 3-stage cp.async, XOR-swizzled 32B rows (no padding),
// ONE __syncthreads per k-step.
// Swizzle: chunk j at row r lives at j^((r>>2)&1); any 8 consecutive
// rows hit 8 distinct 16B bank-groups -> conflict-free ldmatrix.
// =============================================================
#define TILE_SB (128 * 32)          // 4096 B

__global__ void __launch_bounds__(512, 1)
gemm_mma(const ushort_t* __restrict__ Ah, const ushort_t* __restrict__ Al,
         const ushort_t* __restrict__ Bh, const ushort_t* __restrict__ Bl,
         float* __restrict__ C) {
    __shared__ __align__(16) unsigned char sb[3][4][TILE_SB];   // 49152 B

    int tid = threadIdx.x, wid = tid >> 5, lane = tid & 31;
    int warpM = wid >> 3, warpN = wid & 7;
    size_t bm = (size_t)blockIdx.y * 128, bn = (size_t)blockIdx.x * 128;

    const ushort_t* srcs[4] = { Ah + bm * EE, Al + bm * EE,
                                Bh + bn * EE, Bl + bn * EE };

    float acc[4][2][4];
#pragma unroll
    for (int mt = 0; mt < 4; mt++)
#pragma unroll
        for (int nt = 0; nt < 2; nt++)
#pragma unroll
            for (int e = 0; e < 4; e++) acc[mt][nt][e] = 0.f;

    // per-lane ldmatrix row/chunk (pre-swizzle)
    int a_row = (lane & 7) + ((lane >> 3) & 1) * 8;
    int a_chk = (lane >> 4) & 1;
    int b_row = (lane & 7) + ((lane >= 16) ? 8 : 0);
    int b_chk = (lane >> 3) & 1;

#define ISSUE_STAGE(s, kt)                                                     \
    {                                                                          \
        _Pragma("unroll")                                                      \
        for (int hh = 0; hh < 2; hh++) {                                       \
            int i = tid + hh * 512;                                            \
            int t = i >> 8, rem = i & 255, r = rem >> 1, j = rem & 1;          \
            const void* g = (const void*)(srcs[t] + (size_t)r * EE + (kt) + j * 8); \
            int jj = j ^ ((r >> 2) & 1);                                       \
            uint32_t d = smem_u32(&sb[s][t][r * 32 + jj * 16]);                \
            asm volatile("cp.async.cg.shared.global [%0], [%1], 16;"           \
                         :: "r"(d), "l"(g));                                   \
        }                                                                      \
        asm volatile("cp.async.commit_group;" ::: "memory");                   \
    }

    ISSUE_STAGE(0, 0)
    ISSUE_STAGE(1, 16)

#pragma unroll 1
    for (int c = 0; c < EE / 16; c++) {
        asm volatile("cp.async.wait_group 1;" ::: "memory");
        __syncthreads();
        // stage (c+2)%3 was last read at iter c-1 (or never); safe to refill now
        if (c + 2 < EE / 16) ISSUE_STAGE((c + 2) % 3, (c + 2) * 16)

        int s = c % 3;
        uint32_t ahf[4][4], alf[4][4], bhf[4], blf[4];
        {
            int r2 = warpN * 16 + b_row;
            int ch = b_chk ^ ((r2 >> 2) & 1);
            LDSM4(bhf, smem_u32(&sb[s][2][r2 * 32 + ch * 16]));
            LDSM4(blf, smem_u32(&sb[s][3][r2 * 32 + ch * 16]));
        }
#pragma unroll
        for (int mt = 0; mt < 4; mt++) {
            int r1 = warpM * 64 + mt * 16 + a_row;
            int ch = a_chk ^ ((r1 >> 2) & 1);
            LDSM4(ahf[mt], smem_u32(&sb[s][0][r1 * 32 + ch * 16]));
            LDSM4(alf[mt], smem_u32(&sb[s][1][r1 * 32 + ch * 16]));
        }
#pragma unroll
        for (int mt = 0; mt < 4; mt++)
#pragma unroll
            for (int nt = 0; nt < 2; nt++) {
                MMA16816(acc[mt][nt], ahf[mt], bhf[2 * nt], bhf[2 * nt + 1]);
                MMA16816(acc[mt][nt], ahf[mt], blf[2 * nt], blf[2 * nt + 1]);
                MMA16816(acc[mt][nt], alf[mt], bhf[2 * nt], bhf[2 * nt + 1]);
            }
    }

    int r0 = lane >> 2, c0 = (lane & 3) * 2;
#pragma unroll
    for (int mt = 0; mt < 4; mt++)
#pragma unroll
        for (int nt = 0; nt < 2; nt++) {
            float* p = C + (bm + warpM * 64 + mt * 16 + r0) * EE
                         + bn + warpN * 16 + nt * 8 + c0;
            p[0] = acc[mt][nt][0];
            p[1] = acc[mt][nt][1];
            p += 8 * EE;
            p[0] = acc[mt][nt][2];
            p[1] = acc[mt][nt][3];
        }
#undef ISSUE_STAGE
}

// =============================================================
// split fp32 -> (hi, lo) bf16
// =============================================================
__global__ void __launch_bounds__(256)
split_f32(const float* __restrict__ A, ushort_t* __restrict__ H,
          ushort_t* __restrict__ L) {
    int i = blockIdx.x * 256 + threadIdx.x;
    float4 v = ((const float4*)A)[i];
    float f[4] = {v.x, v.y, v.z, v.w};
    ushort_t h[4], l[4];
#pragma unroll
    for (int j = 0; j < 4; j++) {
        bf16 hb = __float2bfloat16(f[j]);
        bf16 lb = __float2bfloat16(f[j] - __bfloat162float(hb));
        h[j] = *(ushort_t*)&hb;
        l[j] = *(ushort_t*)&lb;
    }
    *(uint2*)(H + (size_t)i * 4) = *(uint2*)h;
    *(uint2*)(L + (size_t)i * 4) = *(uint2*)l;
}

// =============================================================
// transpose + split: T[n][k] = W[k][n], bf16 hi/lo
// =============================================================
__global__ void __launch_bounds__(256)
tsplit(const float* __restrict__ W, ushort_t* __restrict__ Th,
       ushort_t* __restrict__ Tl) {
    __shared__ float tile[32][33];
    int bx = blockIdx.x * 32, by = blockIdx.y * 32;
    int tx = threadIdx.x & 31, ty = threadIdx.x >> 5;   // 32 x 8
#pragma unroll
    for (int j = 0; j < 32; j += 8)
        tile[ty + j][tx] = W[(size_t)(by + ty + j) * EE + bx + tx];
    __syncthreads();
#pragma unroll
    for (int j = 0; j < 32; j += 8) {
        float v = tile[tx][ty + j];                      // = W[by+tx][bx+ty+j]
        bf16 hb = __float2bfloat16(v);
        bf16 lb = __float2bfloat16(v - __bfloat162float(hb));
        size_t o = (size_t)(bx + ty + j) * EE + by + tx; // T[bx+ty+j][by+tx]
        Th[o] = *(ushort_t*)&hb;
        Tl[o] = *(ushort_t*)&lb;
    }
}

// =============================================================
// alpha/beta: block = 8 rows, x staged in smem once
// =============================================================
__global__ void __launch_bounds__(256, 4)
ab_kernel(const float* __restrict__ x,
          const float* __restrict__ Wa,
          const float* __restrict__ Wb,
          const float* __restrict__ Alog,
          const float* __restrict__ dtb,
          float4* __restrict__ AB) {
    __shared__ float xs[8][EE];
    int r8 = blockIdx.x;

    const float4* xin = (const float4*)(x + (size_t)r8 * 8 * EE);
    float4* xsp = (float4*)&xs[0][0];
#pragma unroll
    for (int idx = threadIdx.x; idx < 8 * EE / 4; idx += 256)
        xsp[idx] = xin[idx];
    __syncthreads();

    int r = threadIdx.x >> 5;
    int c = threadIdx.x & 31;
    const float* W = (c < 16) ? Wa : Wb;
    int cc = c & 15;

    float a0 = 0.f, a1 = 0.f, a2 = 0.f, a3 = 0.f;
#pragma unroll 8
    for (int k = 0; k < EE; k += 4) {
        a0 = fmaf(xs[r][k+0], W[(size_t)(k+0) * HH + cc], a0);
        a1 = fmaf(xs[r][k+1], W[(size_t)(k+1) * HH + cc], a1);
        a2 = fmaf(xs[r][k+2], W[(size_t)(k+2) * HH + cc], a2);
        a3 = fmaf(xs[r][k+3], W[(size_t)(k+3) * HH + cc], a3);
    }
    float acc = (a0 + a1) + (a2 + a3);

    int row = r8 * 8 + r;
    if (c < 16) {
        float t  = acc + dtb[cc];
        float sp = fmaxf(t, 0.f) + log1pf(expf(-fabsf(t)));
        AB[(size_t)row * HH + cc].x = expf(-expf(Alog[cc]) * sp);
    } else {
        AB[(size_t)row * HH + cc].y = 1.f / (1.f + expf(-acc));
    }
}

// =============================================================
// ℓ2-normalize q (with /sqrt(D)) and k in place; also store k.q
// =============================================================
__global__ void norm_qk(float* __restrict__ Q, float* __restrict__ K,
                        float4* __restrict__ AB) {
    int gw   = blockIdx.x * 8 + (threadIdx.x >> 5);
    int lane = threadIdx.x & 31;
    int row = gw >> 4, h = gw & 15;
    size_t base = (size_t)row * EE + h * DD;

    float2* qp = (float2*)(Q + base);
    float2 qv = qp[lane];
    float ss = fmaf(qv.x, qv.x, qv.y * qv.y);
#pragma unroll
    for (int o = 16; o; o >>= 1) ss += __shfl_xor_sync(0xffffffffu, ss, o);
    float sq = 0.125f / fmaxf(sqrtf(ss), 1e-12f);
    qv.x *= sq; qv.y *= sq;
    qp[lane] = qv;

    float2* kp = (float2*)(K + base);
    float2 kv = kp[lane];
    float sk = fmaf(kv.x, kv.x, kv.y * kv.y);
#pragma unroll
    for (int o = 16; o; o >>= 1) sk += __shfl_xor_sync(0xffffffffu, sk, o);
    float sc = 1.f / fmaxf(sqrtf(sk), 1e-12f);
    kv.x *= sc; kv.y *= sc;
    kp[lane] = kv;

    // k.q for this (row, head) — removes per-step recompute in the scan
    float pd = fmaf(qv.x, kv.x, qv.y * kv.y);
#pragma unroll
    for (int o = 16; o; o >>= 1) pd += __shfl_xor_sync(0xffffffffu, pd, o);
    if (lane == 0) AB[(size_t)row * HH + h].z = pd;
}

// =============================================================
// Delta-rule scan: PF=8 register pipeline; kq precomputed.
//  o = a*(s.q) + delta*kq; chain = s.k reduce -> delta -> update
// =============================================================
#define PF 8

__global__ void __launch_bounds__(128, 1)
scan_kernel(const float* __restrict__ Q, const float* __restrict__ K,
            const float* __restrict__ V, const float4* __restrict__ AB,
            float* __restrict__ O) {
    int bh = blockIdx.y;
    int b = bh >> 4, h = bh & 15;
    int rg = blockIdx.x;
    int tid = threadIdx.x;
    int lr = tid >> 3, c = tid & 7;
    int i = rg * 16 + lr;

    size_t base0 = ((size_t)b * SS) * EE + (size_t)h * DD;
    const float4* Kp = (const float4*)(K + base0);
    const float4* Qp = (const float4*)(Q + base0);
    const float*  Vp = V + base0 + i;
    const float4* ABp = AB + (size_t)b * SS * HH + h;
    float*        Op = O + base0 + i;

    float4 s0 = make_float4(0.f, 0.f, 0.f, 0.f);
    float4 s1 = make_float4(0.f, 0.f, 0.f, 0.f);

    float4 kb0[PF], kb1[PF], qb0[PF], qb1[PF];
    float  vb[PF];
    float4 abb[PF];

#pragma unroll
    for (int j = 0; j < PF; j++) {
        size_t o4 = (size_t)j * (EE / 4);
        kb0[j] = Kp[o4 + c * 2]; kb1[j] = Kp[o4 + c * 2 + 1];
        qb0[j] = Qp[o4 + c * 2]; qb1[j] = Qp[o4 + c * 2 + 1];
        vb[j]  = Vp[(size_t)j * EE];
        abb[j] = ABp[(size_t)j * HH];
    }

#pragma unroll 1
    for (int t = 0; t < SS; t += PF) {
#pragma unroll
        for (int j = 0; j < PF; j++) {
            float4 ck0 = kb0[j], ck1 = kb1[j];
            float4 cq0 = qb0[j], cq1 = qb1[j];
            float  cv  = vb[j];
            float  ca  = abb[j].x, cbe = abb[j].y, ckq = abb[j].z;

            int tn = t + j + PF; if (tn >= SS) tn = SS - 1;
            size_t o4 = (size_t)tn * (EE / 4);
            kb0[j] = Kp[o4 + c * 2]; kb1[j] = Kp[o4 + c * 2 + 1];
            qb0[j] = Qp[o4 + c * 2]; qb1[j] = Qp[o4 + c * 2 + 1];
            vb[j]  = Vp[(size_t)tn * EE];
            abb[j] = ABp[(size_t)tn * HH];

            // two dot partials (s.k critical, s.q off-chain)
            float pk  = ck0.x * s0.x,  pk2 = ck0.y * s0.y;
            float pq  = cq0.x * s0.x,  pq2 = cq0.y * s0.y;
            pk  = fmaf(ck0.z, s0.z, pk);   pk2 = fmaf(ck0.w, s0.w, pk2);
            pq  = fmaf(cq0.z, s0.z, pq);   pq2 = fmaf(cq0.w, s0.w, pq2);
            pk  = fmaf(ck1.x, s1.x, pk);   pk2 = fmaf(ck1.y, s1.y, pk2);
            pq  = fmaf(cq1.x, s1.x, pq);   pq2 = fmaf(cq1.y, s1.y, pq2);
            pk  = fmaf(ck1.z, s1.z, pk);   pk2 = fmaf(ck1.w, s1.w, pk2);
            pq  = fmaf(cq1.z, s1.z, pq);   pq2 = fmaf(cq1.w, s1.w, pq2);
            pk += pk2; pq += pq2;

            pk += __shfl_xor_sync(0xffffffffu, pk, 1);
            pq += __shfl_xor_sync(0xffffffffu, pq, 1);
            pk += __shfl_xor_sync(0xffffffffu, pk, 2);
            pq += __shfl_xor_sync(0xffffffffu, pq, 2);
            pk += __shfl_xor_sync(0xffffffffu, pk, 4);
            pq += __shfl_xor_sync(0xffffffffu, pq, 4);

            float delta = cbe * fmaf(-ca, pk, cv);
            float o = fmaf(ca, pq, delta * ckq);
            if (c == 0) Op[(size_t)(t + j) * EE] = o;

            s0.x = fmaf(ca, s0.x, delta * ck0.x);
            s0.y = fmaf(ca, s0.y, delta * ck0.y);
            s0.z = fmaf(ca, s0.z, delta * ck0.z);
            s0.w = fmaf(ca, s0.w, delta * ck0.w);
            s1.x = fmaf(ca, s1.x, delta * ck1.x);
            s1.y = fmaf(ca, s1.y, delta * ck1.y);
            s1.z = fmaf(ca, s1.z, delta * ck1.z);
            s1.w = fmaf(ca, s1.w, delta * ck1.w);
        }
    }
}

// =============================================================
// RMSNorm + rms_w + SiLU(gate), fused with bf16 hi/lo split output
// =============================================================
__global__ void rms_gate_split(const float* __restrict__ O, const float* __restrict__ G,
                               const float* __restrict__ rmsw,
                               ushort_t* __restrict__ YH, ushort_t* __restrict__ YL) {
    int gw   = blockIdx.x * 8 + (threadIdx.x >> 5);
    int lane = threadIdx.x & 31;
    int row = gw >> 4, h = gw & 15;
    size_t base = (size_t)row * EE + h * DD;

    float2 ov = ((const float2*)(O + base))[lane];
    float ss = fmaf(ov.x, ov.x, ov.y * ov.y);
#pragma unroll
    for (int o = 16; o; o >>= 1) ss += __shfl_xor_sync(0xffffffffu, ss, o);
    float scale = 1.f / sqrtf(ss * (1.f / 64.f) + 1e-6f);

    float2 gv = ((const float2*)(G + base))[lane];
    float gx = gv.x / (1.f + expf(-gv.x));
    float gy = gv.y / (1.f + expf(-gv.y));
    float2 rw = ((const float2*)rmsw)[lane];

    float yx = ov.x * scale * rw.x * gx;
    float yy = ov.y * scale * rw.y * gy;

    bf16 hx = __float2bfloat16(yx);
    bf16 hy = __float2bfloat16(yy);
    bf16 lx = __float2bfloat16(yx - __bfloat162float(hx));
    bf16 ly = __float2bfloat16(yy - __bfloat162float(hy));
    ushort_t hp[2] = { *(ushort_t*)&hx, *(ushort_t*)&hy };
    ushort_t lp[2] = { *(ushort_t*)&lx, *(ushort_t*)&ly };
    ((uint32_t*)(YH + base))[lane] = *(uint32_t*)hp;
    ((uint32_t*)(YL + base))[lane] = *(uint32_t*)lp;
}

// =============================================================
extern "C" void kernel_launch(void* const* d_in, const int* in_sizes, int n_in,
                              void* d_out, int out_size) {
    const float* x     = (const float*)d_in[0];
    const float* Wq    = (const float*)d_in[1];
    const float* Wk    = (const float*)d_in[2];
    const float* Wv    = (const float*)d_in[3];
    const float* Wa    = (const float*)d_in[4];
    const float* Wb    = (const float*)d_in[5];
    const float* Alog  = (const float*)d_in[6];
    const float* dtb   = (const float*)d_in[7];
    const float* Wg    = (const float*)d_in[8];
    const float* Wout  = (const float*)d_in[9];
    const float* rmsw  = (const float*)d_in[10];

    float *bq, *bk, *bv, *bg, *bo;
    float4* ab;
    ushort_t *xh, *xl, *yh, *yl;
    ushort_t *wqh, *wql, *wkh, *wkl, *wvh, *wvl, *wgh, *wgl, *woh, *wol;
    cudaGetSymbolAddress((void**)&bq, g_bq);
    cudaGetSymbolAddress((void**)&bk, g_bk);
    cudaGetSymbolAddress((void**)&bv, g_bv);
    cudaGetSymbolAddress((void**)&bg, g_bg);
    cudaGetSymbolAddress((void**)&bo, g_bo);
    cudaGetSymbolAddress((void**)&ab, g_ab4);
    cudaGetSymbolAddress((void**)&xh, g_xh);
    cudaGetSymbolAddress((void**)&xl, g_xl);
    cudaGetSymbolAddress((void**)&yh, g_yh);
    cudaGetSymbolAddress((void**)&yl, g_yl);
    cudaGetSymbolAddress((void**)&wqh, g_wq_h); cudaGetSymbolAddress((void**)&wql, g_wq_l);
    cudaGetSymbolAddress((void**)&wkh, g_wk_h); cudaGetSymbolAddress((void**)&wkl, g_wk_l);
    cudaGetSymbolAddress((void**)&wvh, g_wv_h); cudaGetSymbolAddress((void**)&wvl, g_wv_l);
    cudaGetSymbolAddress((void**)&wgh, g_wg_h); cudaGetSymbolAddress((void**)&wgl, g_wg_l);
    cudaGetSymbolAddress((void**)&woh, g_wo_h); cudaGetSymbolAddress((void**)&wol, g_wo_l);

    dim3 tgrid(32, 32), tblk(256);
    split_f32<<<ROWS * EE / 1024, 256>>>(x, xh, xl);
    tsplit<<<tgrid, tblk>>>(Wq, wqh, wql);
    tsplit<<<tgrid, tblk>>>(Wk, wkh, wkl);
    tsplit<<<tgrid, tblk>>>(Wv, wvh, wvl);
    tsplit<<<tgrid, tblk>>>(Wg, wgh, wgl);
    tsplit<<<tgrid, tblk>>>(Wout, woh, wol);

    dim3 gg(EE / 128, ROWS / 128);   // (8, 64)
    gemm_mma<<<gg, 512>>>(xh, xl, wqh, wql, bq);
    gemm_mma<<<gg, 512>>>(xh, xl, wkh, wkl, bk);
    gemm_mma<<<gg, 512>>>(xh, xl, wvh, wvl, bv);
    gemm_mma<<<gg, 512>>>(xh, xl, wgh, wgl, bg);

    ab_kernel<<<ROWS / 8, 256>>>(x, Wa, Wb, Alog, dtb, ab);
    norm_qk<<<ROWS * HH / 8, 256>>>(bq, bk, ab);

    scan_kernel<<<dim3(4, BB * HH), 128>>>(bq, bk, bv, ab, bo);

    rms_gate_split<<<ROWS * HH / 8, 256>>>(bo, bg, rmsw, yh, yl);

    gemm_mma<<<gg, 512>>>(yh, yl, woh, wol, (float*)d_out);
}

// round 8
// speedup vs baseline: 1.0689x; 1.0689x over previous
#include <cuda_runtime.h>
#include <cuda_bf16.h>
#include <math.h>
#include <stdint.h>

// Problem dims (fixed)
#define BB 2
#define SS 4096
#define EE 1024
#define HH 16
#define DD 64
#define ROWS (BB*SS)          // 8192

typedef __nv_bfloat16 bf16;
typedef unsigned short ushort_t;

// ---------------- scratch (no allocs allowed) ----------------
__device__ float  g_bq[ROWS*EE];
__device__ float  g_bk[ROWS*EE];
__device__ float  g_bv[ROWS*EE];
__device__ float  g_bg[ROWS*EE];
__device__ float  g_bo[ROWS*EE];
__device__ float2 g_ab[ROWS*HH];   // (alpha, beta)
__device__ float  g_kq[ROWS*HH];   // k.q per (row, head)

__device__ ushort_t g_xh[ROWS*EE];
__device__ ushort_t g_xl[ROWS*EE];
__device__ ushort_t g_yh[ROWS*EE];
__device__ ushort_t g_yl[ROWS*EE];
__device__ ushort_t g_wq_h[EE*EE], g_wq_l[EE*EE];
__device__ ushort_t g_wk_h[EE*EE], g_wk_l[EE*EE];
__device__ ushort_t g_wv_h[EE*EE], g_wv_l[EE*EE];
__device__ ushort_t g_wg_h[EE*EE], g_wg_l[EE*EE];
__device__ ushort_t g_wo_h[EE*EE], g_wo_l[EE*EE];

__device__ __forceinline__ uint32_t smem_u32(const void* p) {
    uint32_t a;
    asm("{ .reg .u64 t; cvta.to.shared.u64 t, %1; cvt.u32.u64 %0, t; }" : "=r"(a) : "l"(p));
    return a;
}

#define LDSM4(r, addr) \
    asm volatile("ldmatrix.sync.aligned.m8n8.x4.shared.b16 {%0,%1,%2,%3}, [%4];" \
        : "=r"((r)[0]), "=r"((r)[1]), "=r"((r)[2]), "=r"((r)[3]) : "r"(addr))

#define MMA16816(d, a, b0, b1) \
    asm volatile("mma.sync.aligned.m16n8k16.row.col.f32.bf16.bf16.f32 " \
        "{%0,%1,%2,%3},{%4,%5,%6,%7},{%8,%9},{%0,%1,%2,%3};" \
        : "+f"((d)[0]), "+f"((d)[1]), "+f"((d)[2]), "+f"((d)[3]) \
        : "r"((a)[0]), "r"((a)[1]), "r"((a)[2]), "r"((a)[3]), "r"(b0), "r"(b1))

// =============================================================
// split-bf16 GEMM on mma.sync (R6-proven version, unchanged):
// C[8192,1024] = A @ Bt^T, fp32 acc; C = Ah*Bh + Ah*Bl + Al*Bh
// CTA 128x128, 512 thr, warp tile 64x16, BK=16, 2-stage cp.async,
// 48B-padded rows (conflict-free ldmatrix).
// =============================================================
#define RSTRIDE 48
#define TILE_SB (128 * RSTRIDE)     // 6144 per operand tile

__global__ void __launch_bounds__(512, 1)
gemm_mma(const ushort_t* __restrict__ Ah, const ushort_t* __restrict__ Al,
         const ushort_t* __restrict__ Bh, const ushort_t* __restrict__ Bl,
         float* __restrict__ C) {
    __shared__ __align__(16) unsigned char sb[2][4][TILE_SB];   // 49152 B

    int tid = threadIdx.x, wid = tid >> 5, lane = tid & 31;
    int warpM = wid >> 3, warpN = wid & 7;
    size_t bm = (size_t)blockIdx.y * 128, bn = (size_t)blockIdx.x * 128;

    const ushort_t* srcs[4] = { Ah + bm * EE, Al + bm * EE,
                                Bh + bn * EE, Bl + bn * EE };

    float acc[4][2][4];
#pragma unroll
    for (int mt = 0; mt < 4; mt++)
#pragma unroll
        for (int nt = 0; nt < 2; nt++)
#pragma unroll
            for (int e = 0; e < 4; e++) acc[mt][nt][e] = 0.f;

    int a_row = (lane & 7) + ((lane >> 3) & 1) * 8;
    int a_chk = (lane >> 4) & 1;
    int b_row = (lane & 7) + ((lane >= 16) ? 8 : 0);
    int b_chk = (lane >> 3) & 1;

#define ISSUE_STAGE(s, kt)                                                     \
    {                                                                          \
        _Pragma("unroll")                                                      \
        for (int hh = 0; hh < 2; hh++) {                                       \
            int i = tid + hh * 512;                                            \
            int t = i >> 8, rem = i & 255, r = rem >> 1, j = rem & 1;          \
            const void* g = (const void*)(srcs[t] + (size_t)r * EE + (kt) + j * 8); \
            uint32_t d = smem_u32(&sb[s][t][r * RSTRIDE + j * 16]);            \
            asm volatile("cp.async.cg.shared.global [%0], [%1], 16;"           \
                         :: "r"(d), "l"(g));                                   \
        }                                                                      \
        asm volatile("cp.async.commit_group;" ::: "memory");                   \
    }

    ISSUE_STAGE(0, 0)
    ISSUE_STAGE(1, 16)

#pragma unroll 1
    for (int c = 0; c < EE / 16; c++) {
        asm volatile("cp.async.wait_group 1;" ::: "memory");
        __syncthreads();
        int s = c & 1;

        uint32_t ahf[4][4], alf[4][4], bhf[4], blf[4];
        {
            uint32_t ab = smem_u32(&sb[s][2][(warpN * 16 + b_row) * RSTRIDE + b_chk * 16]);
            LDSM4(bhf, ab);
            uint32_t ab2 = smem_u32(&sb[s][3][(warpN * 16 + b_row) * RSTRIDE + b_chk * 16]);
            LDSM4(blf, ab2);
        }
#pragma unroll
        for (int mt = 0; mt < 4; mt++) {
            uint32_t aa = smem_u32(&sb[s][0][(warpM * 64 + mt * 16 + a_row) * RSTRIDE + a_chk * 16]);
            LDSM4(ahf[mt], aa);
            uint32_t aa2 = smem_u32(&sb[s][1][(warpM * 64 + mt * 16 + a_row) * RSTRIDE + a_chk * 16]);
            LDSM4(alf[mt], aa2);
        }
#pragma unroll
        for (int mt = 0; mt < 4; mt++)
#pragma unroll
            for (int nt = 0; nt < 2; nt++) {
                MMA16816(acc[mt][nt], ahf[mt], bhf[2 * nt], bhf[2 * nt + 1]);
                MMA16816(acc[mt][nt], ahf[mt], blf[2 * nt], blf[2 * nt + 1]);
                MMA16816(acc[mt][nt], alf[mt], bhf[2 * nt], bhf[2 * nt + 1]);
            }
        __syncthreads();
        if (c + 2 < EE / 16) ISSUE_STAGE(s, (c + 2) * 16)
    }

    int r0 = lane >> 2, c0 = (lane & 3) * 2;
#pragma unroll
    for (int mt = 0; mt < 4; mt++)
#pragma unroll
        for (int nt = 0; nt < 2; nt++) {
            float* p = C + (bm + warpM * 64 + mt * 16 + r0) * EE
                         + bn + warpN * 16 + nt * 8 + c0;
            p[0] = acc[mt][nt][0];
            p[1] = acc[mt][nt][1];
            p += 8 * EE;
            p[0] = acc[mt][nt][2];
            p[1] = acc[mt][nt][3];
        }
#undef ISSUE_STAGE
}

// =============================================================
// split fp32 -> (hi, lo) bf16
// =============================================================
__global__ void __launch_bounds__(256)
split_f32(const float* __restrict__ A, ushort_t* __restrict__ H,
          ushort_t* __restrict__ L) {
    int i = blockIdx.x * 256 + threadIdx.x;
    float4 v = ((const float4*)A)[i];
    float f[4] = {v.x, v.y, v.z, v.w};
    ushort_t h[4], l[4];
#pragma unroll
    for (int j = 0; j < 4; j++) {
        bf16 hb = __float2bfloat16(f[j]);
        bf16 lb = __float2bfloat16(f[j] - __bfloat162float(hb));
        h[j] = *(ushort_t*)&hb;
        l[j] = *(ushort_t*)&lb;
    }
    *(uint2*)(H + (size_t)i * 4) = *(uint2*)h;
    *(uint2*)(L + (size_t)i * 4) = *(uint2*)l;
}

// =============================================================
// transpose + split: T[n][k] = W[k][n], bf16 hi/lo
// =============================================================
__global__ void __launch_bounds__(256)
tsplit(const float* __restrict__ W, ushort_t* __restrict__ Th,
       ushort_t* __restrict__ Tl) {
    __shared__ float tile[32][33];
    int bx = blockIdx.x * 32, by = blockIdx.y * 32;
    int tx = threadIdx.x & 31, ty = threadIdx.x >> 5;   // 32 x 8
#pragma unroll
    for (int j = 0; j < 32; j += 8)
        tile[ty + j][tx] = W[(size_t)(by + ty + j) * EE + bx + tx];
    __syncthreads();
#pragma unroll
    for (int j = 0; j < 32; j += 8) {
        float v = tile[tx][ty + j];                      // = W[by+tx][bx+ty+j]
        bf16 hb = __float2bfloat16(v);
        bf16 lb = __float2bfloat16(v - __bfloat162float(hb));
        size_t o = (size_t)(bx + ty + j) * EE + by + tx; // T[bx+ty+j][by+tx]
        Th[o] = *(ushort_t*)&hb;
        Tl[o] = *(ushort_t*)&lb;
    }
}

// =============================================================
// alpha/beta: block = 8 rows, x staged in smem once (R6 version)
// =============================================================
__global__ void __launch_bounds__(256, 4)
ab_kernel(const float* __restrict__ x,
          const float* __restrict__ Wa,
          const float* __restrict__ Wb,
          const float* __restrict__ Alog,
          const float* __restrict__ dtb,
          float2* __restrict__ AB) {
    __shared__ float xs[8][EE];
    int r8 = blockIdx.x;

    const float4* xin = (const float4*)(x + (size_t)r8 * 8 * EE);
    float4* xsp = (float4*)&xs[0][0];
#pragma unroll
    for (int idx = threadIdx.x; idx < 8 * EE / 4; idx += 256)
        xsp[idx] = xin[idx];
    __syncthreads();

    int r = threadIdx.x >> 5;
    int c = threadIdx.x & 31;
    const float* W = (c < 16) ? Wa : Wb;
    int cc = c & 15;

    float a0 = 0.f, a1 = 0.f, a2 = 0.f, a3 = 0.f;
#pragma unroll 8
    for (int k = 0; k < EE; k += 4) {
        a0 = fmaf(xs[r][k+0], W[(size_t)(k+0) * HH + cc], a0);
        a1 = fmaf(xs[r][k+1], W[(size_t)(k+1) * HH + cc], a1);
        a2 = fmaf(xs[r][k+2], W[(size_t)(k+2) * HH + cc], a2);
        a3 = fmaf(xs[r][k+3], W[(size_t)(k+3) * HH + cc], a3);
    }
    float acc = (a0 + a1) + (a2 + a3);

    int row = r8 * 8 + r;
    if (c < 16) {
        float t  = acc + dtb[cc];
        float sp = fmaxf(t, 0.f) + log1pf(expf(-fabsf(t)));
        AB[(size_t)row * HH + cc].x = expf(-expf(Alog[cc]) * sp);
    } else {
        AB[(size_t)row * HH + cc].y = 1.f / (1.f + expf(-acc));
    }
}

// =============================================================
// ℓ2-normalize q (with /sqrt(D)) and k in place; also store k.q
// =============================================================
__global__ void norm_qk(float* __restrict__ Q, float* __restrict__ K,
                        float* __restrict__ KQ) {
    int gw   = blockIdx.x * 8 + (threadIdx.x >> 5);
    int lane = threadIdx.x & 31;
    int row = gw >> 4, h = gw & 15;
    size_t base = (size_t)row * EE + h * DD;

    float2* qp = (float2*)(Q + base);
    float2 qv = qp[lane];
    float ss = fmaf(qv.x, qv.x, qv.y * qv.y);
#pragma unroll
    for (int o = 16; o; o >>= 1) ss += __shfl_xor_sync(0xffffffffu, ss, o);
    float sq = 0.125f / fmaxf(sqrtf(ss), 1e-12f);
    qv.x *= sq; qv.y *= sq;
    qp[lane] = qv;

    float2* kp = (float2*)(K + base);
    float2 kv = kp[lane];
    float sk = fmaf(kv.x, kv.x, kv.y * kv.y);
#pragma unroll
    for (int o = 16; o; o >>= 1) sk += __shfl_xor_sync(0xffffffffu, sk, o);
    float sc = 1.f / fmaxf(sqrtf(sk), 1e-12f);
    kv.x *= sc; kv.y *= sc;
    kp[lane] = kv;

    float pd = fmaf(qv.x, kv.x, qv.y * kv.y);
#pragma unroll
    for (int o = 16; o; o >>= 1) pd += __shfl_xor_sync(0xffffffffu, pd, o);
    if (lane == 0) KQ[(size_t)row * HH + h] = pd;
}

// =============================================================
// Delta-rule scan: PF=8 register pipeline; kq from precomputed array.
//  o = a*(s.q) + delta*kq; chain = s.k reduce -> delta -> update
// =============================================================
#define PF 8

__global__ void __launch_bounds__(128, 1)
scan_kernel(const float* __restrict__ Q, const float* __restrict__ K,
            const float* __restrict__ V, const float2* __restrict__ AB,
            const float* __restrict__ KQ, float* __restrict__ O) {
    int bh = blockIdx.y;
    int b = bh >> 4, h = bh & 15;
    int rg = blockIdx.x;
    int tid = threadIdx.x;
    int lr = tid >> 3, c = tid & 7;
    int i = rg * 16 + lr;

    size_t base0 = ((size_t)b * SS) * EE + (size_t)h * DD;
    const float4* Kp = (const float4*)(K + base0);
    const float4* Qp = (const float4*)(Q + base0);
    const float*  Vp = V + base0 + i;
    const float2* ABp = AB + (size_t)b * SS * HH + h;
    const float*  KQp = KQ + (size_t)b * SS * HH + h;
    float*        Op = O + base0 + i;

    float4 s0 = make_float4(0.f, 0.f, 0.f, 0.f);
    float4 s1 = make_float4(0.f, 0.f, 0.f, 0.f);

    float4 kb0[PF], kb1[PF], qb0[PF], qb1[PF];
    float  vb[PF], kqb[PF];
    float2 abb[PF];

#pragma unroll
    for (int j = 0; j < PF; j++) {
        size_t o4 = (size_t)j * (EE / 4);
        kb0[j] = Kp[o4 + c * 2]; kb1[j] = Kp[o4 + c * 2 + 1];
        qb0[j] = Qp[o4 + c * 2]; qb1[j] = Qp[o4 + c * 2 + 1];
        vb[j]  = Vp[(size_t)j * EE];
        abb[j] = ABp[(size_t)j * HH];
        kqb[j] = KQp[(size_t)j * HH];
    }

#pragma unroll 1
    for (int t = 0; t < SS; t += PF) {
#pragma unroll
        for (int j = 0; j < PF; j++) {
            float4 ck0 = kb0[j], ck1 = kb1[j];
            float4 cq0 = qb0[j], cq1 = qb1[j];
            float  cv  = vb[j];
            float  ca  = abb[j].x, cbe = abb[j].y, ckq = kqb[j];

            int tn = t + j + PF; if (tn >= SS) tn = SS - 1;
            size_t o4 = (size_t)tn * (EE / 4);
            kb0[j] = Kp[o4 + c * 2]; kb1[j] = Kp[o4 + c * 2 + 1];
            qb0[j] = Qp[o4 + c * 2]; qb1[j] = Qp[o4 + c * 2 + 1];
            vb[j]  = Vp[(size_t)tn * EE];
            abb[j] = ABp[(size_t)tn * HH];
            kqb[j] = KQp[(size_t)tn * HH];

            // two dot partials (s.k critical, s.q off-chain)
            float pk  = ck0.x * s0.x,  pk2 = ck0.y * s0.y;
            float pq  = cq0.x * s0.x,  pq2 = cq0.y * s0.y;
            pk  = fmaf(ck0.z, s0.z, pk);   pk2 = fmaf(ck0.w, s0.w, pk2);
            pq  = fmaf(cq0.z, s0.z, pq);   pq2 = fmaf(cq0.w, s0.w, pq2);
            pk  = fmaf(ck1.x, s1.x, pk);   pk2 = fmaf(ck1.y, s1.y, pk2);
            pq  = fmaf(cq1.x, s1.x, pq);   pq2 = fmaf(cq1.y, s1.y, pq2);
            pk  = fmaf(ck1.z, s1.z, pk);   pk2 = fmaf(ck1.w, s1.w, pk2);
            pq  = fmaf(cq1.z, s1.z, pq);   pq2 = fmaf(cq1.w, s1.w, pq2);
            pk += pk2; pq += pq2;

            pk += __shfl_xor_sync(0xffffffffu, pk, 1);
            pq += __shfl_xor_sync(0xffffffffu, pq, 1);
            pk += __shfl_xor_sync(0xffffffffu, pk, 2);
            pq += __shfl_xor_sync(0xffffffffu, pq, 2);
            pk += __shfl_xor_sync(0xffffffffu, pk, 4);
            pq += __shfl_xor_sync(0xffffffffu, pq, 4);

            float delta = cbe * fmaf(-ca, pk, cv);
            float o = fmaf(ca, pq, delta * ckq);
            if (c == 0) Op[(size_t)(t + j) * EE] = o;

            s0.x = fmaf(ca, s0.x, delta * ck0.x);
            s0.y = fmaf(ca, s0.y, delta * ck0.y);
            s0.z = fmaf(ca, s0.z, delta * ck0.z);
            s0.w = fmaf(ca, s0.w, delta * ck0.w);
            s1.x = fmaf(ca, s1.x, delta * ck1.x);
            s1.y = fmaf(ca, s1.y, delta * ck1.y);
            s1.z = fmaf(ca, s1.z, delta * ck1.z);
            s1.w = fmaf(ca, s1.w, delta * ck1.w);
        }
    }
}

// =============================================================
// RMSNorm + rms_w + SiLU(gate), fused bf16 hi/lo split output
// =============================================================
__global__ void rms_gate_split(const float* __restrict__ O, const float* __restrict__ G,
                               const float* __restrict__ rmsw,
                               ushort_t* __restrict__ YH, ushort_t* __restrict__ YL) {
    int gw   = blockIdx.x * 8 + (threadIdx.x >> 5);
    int lane = threadIdx.x & 31;
    int row = gw >> 4, h = gw & 15;
    size_t base = (size_t)row * EE + h * DD;

    float2 ov = ((const float2*)(O + base))[lane];
    float ss = fmaf(ov.x, ov.x, ov.y * ov.y);
#pragma unroll
    for (int o = 16; o; o >>= 1) ss += __shfl_xor_sync(0xffffffffu, ss, o);
    float scale = 1.f / sqrtf(ss * (1.f / 64.f) + 1e-6f);

    float2 gv = ((const float2*)(G + base))[lane];
    float gx = gv.x / (1.f + expf(-gv.x));
    float gy = gv.y / (1.f + expf(-gv.y));
    float2 rw = ((const float2*)rmsw)[lane];

    float yx = ov.x * scale * rw.x * gx;
    float yy = ov.y * scale * rw.y * gy;

    bf16 hx = __float2bfloat16(yx);
    bf16 hy = __float2bfloat16(yy);
    bf16 lx = __float2bfloat16(yx - __bfloat162float(hx));
    bf16 ly = __float2bfloat16(yy - __bfloat162float(hy));
    ushort_t hp[2] = { *(ushort_t*)&hx, *(ushort_t*)&hy };
    ushort_t lp[2] = { *(ushort_t*)&lx, *(ushort_t*)&ly };
    ((uint32_t*)(YH + base))[lane] = *(uint32_t*)hp;
    ((uint32_t*)(YL + base))[lane] = *(uint32_t*)lp;
}

// =============================================================
extern "C" void kernel_launch(void* const* d_in, const int* in_sizes, int n_in,
                              void* d_out, int out_size) {
    const float* x     = (const float*)d_in[0];
    const float* Wq    = (const float*)d_in[1];
    const float* Wk    = (const float*)d_in[2];
    const float* Wv    = (const float*)d_in[3];
    const float* Wa    = (const float*)d_in[4];
    const float* Wb    = (const float*)d_in[5];
    const float* Alog  = (const float*)d_in[6];
    const float* dtb   = (const float*)d_in[7];
    const float* Wg    = (const float*)d_in[8];
    const float* Wout  = (const float*)d_in[9];
    const float* rmsw  = (const float*)d_in[10];

    float *bq, *bk, *bv, *bg, *bo, *kq;
    float2* ab;
    ushort_t *xh, *xl, *yh, *yl;
    ushort_t *wqh, *wql, *wkh, *wkl, *wvh, *wvl, *wgh, *wgl, *woh, *wol;
    cudaGetSymbolAddress((void**)&bq, g_bq);
    cudaGetSymbolAddress((void**)&bk, g_bk);
    cudaGetSymbolAddress((void**)&bv, g_bv);
    cudaGetSymbolAddress((void**)&bg, g_bg);
    cudaGetSymbolAddress((void**)&bo, g_bo);
    cudaGetSymbolAddress((void**)&ab, g_ab);
    cudaGetSymbolAddress((void**)&kq, g_kq);
    cudaGetSymbolAddress((void**)&xh, g_xh);
    cudaGetSymbolAddress((void**)&xl, g_xl);
    cudaGetSymbolAddress((void**)&yh, g_yh);
    cudaGetSymbolAddress((void**)&yl, g_yl);
    cudaGetSymbolAddress((void**)&wqh, g_wq_h); cudaGetSymbolAddress((void**)&wql, g_wq_l);
    cudaGetSymbolAddress((void**)&wkh, g_wk_h); cudaGetSymbolAddress((void**)&wkl, g_wk_l);
    cudaGetSymbolAddress((void**)&wvh, g_wv_h); cudaGetSymbolAddress((void**)&wvl, g_wv_l);
    cudaGetSymbolAddress((void**)&wgh, g_wg_h); cudaGetSymbolAddress((void**)&wgl, g_wg_l);
    cudaGetSymbolAddress((void**)&woh, g_wo_h); cudaGetSymbolAddress((void**)&wol, g_wo_l);

    dim3 tgrid(32, 32), tblk(256);
    split_f32<<<ROWS * EE / 1024, 256>>>(x, xh, xl);
    tsplit<<<tgrid, tblk>>>(Wq, wqh, wql);
    tsplit<<<tgrid, tblk>>>(Wk, wkh, wkl);
    tsplit<<<tgrid, tblk>>>(Wv, wvh, wvl);
    tsplit<<<tgrid, tblk>>>(Wg, wgh, wgl);
    tsplit<<<tgrid, tblk>>>(Wout, woh, wol);

    dim3 gg(EE / 128, ROWS / 128);   // (8, 64)
    gemm_mma<<<gg, 512>>>(xh, xl, wqh, wql, bq);
    gemm_mma<<<gg, 512>>>(xh, xl, wkh, wkl, bk);
    gemm_mma<<<gg, 512>>>(xh, xl, wvh, wvl, bv);
    gemm_mma<<<gg, 512>>>(xh, xl, wgh, wgl, bg);

    ab_kernel<<<ROWS / 8, 256>>>(x, Wa, Wb, Alog, dtb, ab);
    norm_qk<<<ROWS * HH / 8, 256>>>(bq, bk, kq);

    scan_kernel<<<dim3(4, BB * HH), 128>>>(bq, bk, bv, ab, kq, bo);

    rms_gate_split<<<ROWS * HH / 8, 256>>>(bo, bg, rmsw, yh, yl);

    gemm_mma<<<gg, 512>>>(yh, yl, woh, wol, (float*)d_out);
}

// round 9
// speedup vs baseline: 1.3058x; 1.2216x over previous
#include <cuda_runtime.h>
#include <cuda_bf16.h>
#include <math.h>
#include <stdint.h>

// Problem dims (fixed)
#define BB 2
#define SS 4096
#define EE 1024
#define HH 16
#define DD 64
#define ROWS (BB*SS)          // 8192

typedef __nv_bfloat16 bf16;
typedef unsigned short ushort_t;

// ---------------- scratch (no allocs allowed) ----------------
__device__ float  g_bq[ROWS*EE];
__device__ float  g_bk[ROWS*EE];
__device__ float  g_bv[ROWS*EE];
__device__ float  g_bg[ROWS*EE];
__device__ float  g_bo[ROWS*EE];
__device__ float2 g_ab[ROWS*HH];   // (alpha, beta)

__device__ ushort_t g_xh[ROWS*EE];
__device__ ushort_t g_xl[ROWS*EE];
__device__ ushort_t g_yh[ROWS*EE];
__device__ ushort_t g_yl[ROWS*EE];
__device__ ushort_t g_wq_h[EE*EE], g_wq_l[EE*EE];
__device__ ushort_t g_wk_h[EE*EE], g_wk_l[EE*EE];
__device__ ushort_t g_wv_h[EE*EE], g_wv_l[EE*EE];
__device__ ushort_t g_wg_h[EE*EE], g_wg_l[EE*EE];
__device__ ushort_t g_wo_h[EE*EE], g_wo_l[EE*EE];

__device__ __forceinline__ uint32_t smem_u32(const void* p) {
    uint32_t a;
    asm("{ .reg .u64 t; cvta.to.shared.u64 t, %1; cvt.u32.u64 %0, t; }" : "=r"(a) : "l"(p));
    return a;
}

#define LDSM4(r, addr) \
    asm volatile("ldmatrix.sync.aligned.m8n8.x4.shared.b16 {%0,%1,%2,%3}, [%4];" \
        : "=r"((r)[0]), "=r"((r)[1]), "=r"((r)[2]), "=r"((r)[3]) : "r"(addr))

#define MMA16816(d, a, b0, b1) \
    asm volatile("mma.sync.aligned.m16n8k16.row.col.f32.bf16.bf16.f32 " \
        "{%0,%1,%2,%3},{%4,%5,%6,%7},{%8,%9},{%0,%1,%2,%3};" \
        : "+f"((d)[0]), "+f"((d)[1]), "+f"((d)[2]), "+f"((d)[3]) \
        : "r"((a)[0]), "r"((a)[1]), "r"((a)[2]), "r"((a)[3]), "r"(b0), "r"(b1))

// =============================================================
// split-bf16 GEMM on mma.sync: C[8192,1024] = A @ Bt^T, fp32 acc
//   C = Ah*Bh + Ah*Bl + Al*Bh
// v3: CTA 128x64, 256 thr (8 warps, 2m x 4n), warp tile 64x16.
// BK=16, 2-stage cp.async, 48B-padded rows (R6-proven layout).
// smem 36KB, __launch_bounds__(256,2) -> 2 CTAs/SM: cross-CTA
// overlap hides barrier + cp.async stalls that occ=1 exposed.
// =============================================================
#define RSTRIDE 48
#define A_TSB (128 * RSTRIDE)       // 6144 B per A operand tile
#define B_TSB (64 * RSTRIDE)        // 3072 B per B operand tile

__global__ void __launch_bounds__(256, 2)
gemm_mma(const ushort_t* __restrict__ Ah, const ushort_t* __restrict__ Al,
         const ushort_t* __restrict__ Bh, const ushort_t* __restrict__ Bl,
         float* __restrict__ C) {
    __shared__ __align__(16) unsigned char sa[2][2][A_TSB];   // 24576 B
    __shared__ __align__(16) unsigned char sbB[2][2][B_TSB];  // 12288 B

    int tid = threadIdx.x, wid = tid >> 5, lane = tid & 31;
    int warpM = wid >> 2, warpN = wid & 3;
    size_t bm = (size_t)blockIdx.y * 128, bn = (size_t)blockIdx.x * 64;

    const ushort_t* srcA[2] = { Ah + bm * EE, Al + bm * EE };
    const ushort_t* srcB[2] = { Bh + bn * EE, Bl + bn * EE };

    float acc[4][2][4];
#pragma unroll
    for (int mt = 0; mt < 4; mt++)
#pragma unroll
        for (int nt = 0; nt < 2; nt++)
#pragma unroll
            for (int e = 0; e < 4; e++) acc[mt][nt][e] = 0.f;

    int a_row = (lane & 7) + ((lane >> 3) & 1) * 8;
    int a_chk = (lane >> 4) & 1;
    int b_row = (lane & 7) + ((lane >= 16) ? 8 : 0);
    int b_chk = (lane >> 3) & 1;

    // per stage: A = 512 x 16B chunks (2 tiles x 128 rows x 2), B = 256
#define ISSUE_STAGE(s, kt)                                                     \
    {                                                                          \
        _Pragma("unroll")                                                      \
        for (int hh = 0; hh < 2; hh++) {                                       \
            int i = tid + hh * 256;                                            \
            int t = i >> 8, rem = i & 255, r = rem >> 1, j = rem & 1;          \
            const void* g = (const void*)(srcA[t] + (size_t)r * EE + (kt) + j * 8); \
            uint32_t d = smem_u32(&sa[s][t][r * RSTRIDE + j * 16]);            \
            asm volatile("cp.async.cg.shared.global [%0], [%1], 16;"           \
                         :: "r"(d), "l"(g));                                   \
        }                                                                      \
        {                                                                      \
            int t = tid >> 7, rem = tid & 127, r = rem >> 1, j = rem & 1;      \
            const void* g = (const void*)(srcB[t] + (size_t)r * EE + (kt) + j * 8); \
            uint32_t d = smem_u32(&sbB[s][t][r * RSTRIDE + j * 16]);           \
            asm volatile("cp.async.cg.shared.global [%0], [%1], 16;"           \
                         :: "r"(d), "l"(g));                                   \
        }                                                                      \
        asm volatile("cp.async.commit_group;" ::: "memory");                   \
    }

    ISSUE_STAGE(0, 0)
    ISSUE_STAGE(1, 16)

#pragma unroll 1
    for (int c = 0; c < EE / 16; c++) {
        asm volatile("cp.async.wait_group 1;" ::: "memory");
        __syncthreads();
        int s = c & 1;

        uint32_t ahf[4][4], alf[4][4], bhf[4], blf[4];
        {
            uint32_t ab = smem_u32(&sbB[s][0][(warpN * 16 + b_row) * RSTRIDE + b_chk * 16]);
            LDSM4(bhf, ab);
            uint32_t ab2 = smem_u32(&sbB[s][1][(warpN * 16 + b_row) * RSTRIDE + b_chk * 16]);
            LDSM4(blf, ab2);
        }
#pragma unroll
        for (int mt = 0; mt < 4; mt++) {
            uint32_t aa = smem_u32(&sa[s][0][(warpM * 64 + mt * 16 + a_row) * RSTRIDE + a_chk * 16]);
            LDSM4(ahf[mt], aa);
            uint32_t aa2 = smem_u32(&sa[s][1][(warpM * 64 + mt * 16 + a_row) * RSTRIDE + a_chk * 16]);
            LDSM4(alf[mt], aa2);
        }
#pragma unroll
        for (int mt = 0; mt < 4; mt++)
#pragma unroll
            for (int nt = 0; nt < 2; nt++) {
                MMA16816(acc[mt][nt], ahf[mt], bhf[2 * nt], bhf[2 * nt + 1]);
                MMA16816(acc[mt][nt], ahf[mt], blf[2 * nt], blf[2 * nt + 1]);
                MMA16816(acc[mt][nt], alf[mt], bhf[2 * nt], bhf[2 * nt + 1]);
            }
        __syncthreads();
        if (c + 2 < EE / 16) ISSUE_STAGE(s, (c + 2) * 16)
    }

    int r0 = lane >> 2, c0 = (lane & 3) * 2;
#pragma unroll
    for (int mt = 0; mt < 4; mt++)
#pragma unroll
        for (int nt = 0; nt < 2; nt++) {
            float* p = C + (bm + warpM * 64 + mt * 16 + r0) * EE
                         + bn + warpN * 16 + nt * 8 + c0;
            p[0] = acc[mt][nt][0];
            p[1] = acc[mt][nt][1];
            p += 8 * EE;
            p[0] = acc[mt][nt][2];
            p[1] = acc[mt][nt][3];
        }
#undef ISSUE_STAGE
}

// =============================================================
// split fp32 -> (hi, lo) bf16
// =============================================================
__global__ void __launch_bounds__(256)
split_f32(const float* __restrict__ A, ushort_t* __restrict__ H,
          ushort_t* __restrict__ L) {
    int i = blockIdx.x * 256 + threadIdx.x;
    float4 v = ((const float4*)A)[i];
    float f[4] = {v.x, v.y, v.z, v.w};
    ushort_t h[4], l[4];
#pragma unroll
    for (int j = 0; j < 4; j++) {
        bf16 hb = __float2bfloat16(f[j]);
        bf16 lb = __float2bfloat16(f[j] - __bfloat162float(hb));
        h[j] = *(ushort_t*)&hb;
        l[j] = *(ushort_t*)&lb;
    }
    *(uint2*)(H + (size_t)i * 4) = *(uint2*)h;
    *(uint2*)(L + (size_t)i * 4) = *(uint2*)l;
}

// =============================================================
// transpose + split: T[n][k] = W[k][n], bf16 hi/lo
// =============================================================
__global__ void __launch_bounds__(256)
tsplit(const float* __restrict__ W, ushort_t* __restrict__ Th,
       ushort_t* __restrict__ Tl) {
    __shared__ float tile[32][33];
    int bx = blockIdx.x * 32, by = blockIdx.y * 32;
    int tx = threadIdx.x & 31, ty = threadIdx.x >> 5;   // 32 x 8
#pragma unroll
    for (int j = 0; j < 32; j += 8)
        tile[ty + j][tx] = W[(size_t)(by + ty + j) * EE + bx + tx];
    __syncthreads();
#pragma unroll
    for (int j = 0; j < 32; j += 8) {
        float v = tile[tx][ty + j];                      // = W[by+tx][bx+ty+j]
        bf16 hb = __float2bfloat16(v);
        bf16 lb = __float2bfloat16(v - __bfloat162float(hb));
        size_t o = (size_t)(bx + ty + j) * EE + by + tx; // T[bx+ty+j][by+tx]
        Th[o] = *(ushort_t*)&hb;
        Tl[o] = *(ushort_t*)&lb;
    }
}

// =============================================================
// alpha/beta: block = 8 rows, x staged in smem once
// =============================================================
__global__ void __launch_bounds__(256, 4)
ab_kernel(const float* __restrict__ x,
          const float* __restrict__ Wa,
          const float* __restrict__ Wb,
          const float* __restrict__ Alog,
          const float* __restrict__ dtb,
          float2* __restrict__ AB) {
    __shared__ float xs[8][EE];
    int r8 = blockIdx.x;

    const float4* xin = (const float4*)(x + (size_t)r8 * 8 * EE);
    float4* xsp = (float4*)&xs[0][0];
#pragma unroll
    for (int idx = threadIdx.x; idx < 8 * EE / 4; idx += 256)
        xsp[idx] = xin[idx];
    __syncthreads();

    int r = threadIdx.x >> 5;
    int c = threadIdx.x & 31;
    const float* W = (c < 16) ? Wa : Wb;
    int cc = c & 15;

    float a0 = 0.f, a1 = 0.f, a2 = 0.f, a3 = 0.f;
#pragma unroll 8
    for (int k = 0; k < EE; k += 4) {
        a0 = fmaf(xs[r][k+0], W[(size_t)(k+0) * HH + cc], a0);
        a1 = fmaf(xs[r][k+1], W[(size_t)(k+1) * HH + cc], a1);
        a2 = fmaf(xs[r][k+2], W[(size_t)(k+2) * HH + cc], a2);
        a3 = fmaf(xs[r][k+3], W[(size_t)(k+3) * HH + cc], a3);
    }
    float acc = (a0 + a1) + (a2 + a3);

    int row = r8 * 8 + r;
    if (c < 16) {
        float t  = acc + dtb[cc];
        float sp = fmaxf(t, 0.f) + log1pf(expf(-fabsf(t)));
        AB[(size_t)row * HH + cc].x = expf(-expf(Alog[cc]) * sp);
    } else {
        AB[(size_t)row * HH + cc].y = 1.f / (1.f + expf(-acc));
    }
}

// =============================================================
// ℓ2-normalize q (with /sqrt(D)) and k in place (R6 version)
// =============================================================
__global__ void norm_qk(float* __restrict__ Q, float* __restrict__ K) {
    int gw   = blockIdx.x * 8 + (threadIdx.x >> 5);
    int lane = threadIdx.x & 31;
    int row = gw >> 4, h = gw & 15;
    size_t base = (size_t)row * EE + h * DD;

    float2* qp = (float2*)(Q + base);
    float2 qv = qp[lane];
    float ss = fmaf(qv.x, qv.x, qv.y * qv.y);
#pragma unroll
    for (int o = 16; o; o >>= 1) ss += __shfl_xor_sync(0xffffffffu, ss, o);
    float sq = 0.125f / fmaxf(sqrtf(ss), 1e-12f);
    qv.x *= sq; qv.y *= sq;
    qp[lane] = qv;

    float2* kp = (float2*)(K + base);
    float2 kv = kp[lane];
    float sk = fmaf(kv.x, kv.x, kv.y * kv.y);
#pragma unroll
    for (int o = 16; o; o >>= 1) sk += __shfl_xor_sync(0xffffffffu, sk, o);
    float sc = 1.f / fmaxf(sqrtf(sk), 1e-12f);
    kv.x *= sc; kv.y *= sc;
    kp[lane] = kv;
}

// =============================================================
// Delta-rule scan: R6-proven version (PF=8, 3 inline dots).
//  o = a*(s.q) + delta*(k.q); chain = s.k -> delta -> update
// =============================================================
#define PF 8

__global__ void __launch_bounds__(128, 1)
scan_kernel(const float* __restrict__ Q, const float* __restrict__ K,
            const float* __restrict__ V, const float2* __restrict__ AB,
            float* __restrict__ O) {
    int bh = blockIdx.y;
    int b = bh >> 4, h = bh & 15;
    int rg = blockIdx.x;
    int tid = threadIdx.x;
    int lr = tid >> 3, c = tid & 7;
    int i = rg * 16 + lr;

    size_t base0 = ((size_t)b * SS) * EE + (size_t)h * DD;
    const float4* Kp = (const float4*)(K + base0);
    const float4* Qp = (const float4*)(Q + base0);
    const float*  Vp = V + base0 + i;
    const float2* ABp = AB + (size_t)b * SS * HH + h;
    float*        Op = O + base0 + i;

    float4 s0 = make_float4(0.f, 0.f, 0.f, 0.f);
    float4 s1 = make_float4(0.f, 0.f, 0.f, 0.f);

    float4 kb0[PF], kb1[PF], qb0[PF], qb1[PF];
    float  vb[PF];
    float2 abb[PF];

#pragma unroll
    for (int j = 0; j < PF; j++) {
        size_t o4 = (size_t)j * (EE / 4);
        kb0[j] = Kp[o4 + c * 2]; kb1[j] = Kp[o4 + c * 2 + 1];
        qb0[j] = Qp[o4 + c * 2]; qb1[j] = Qp[o4 + c * 2 + 1];
        vb[j]  = Vp[(size_t)j * EE];
        abb[j] = ABp[(size_t)j * HH];
    }

#pragma unroll 1
    for (int t = 0; t < SS; t += PF) {
#pragma unroll
        for (int j = 0; j < PF; j++) {
            float4 ck0 = kb0[j], ck1 = kb1[j];
            float4 cq0 = qb0[j], cq1 = qb1[j];
            float  cv  = vb[j];
            float  ca  = abb[j].x, cbe = abb[j].y;

            int tn = t + j + PF; if (tn >= SS) tn = SS - 1;
            size_t o4 = (size_t)tn * (EE / 4);
            kb0[j] = Kp[o4 + c * 2]; kb1[j] = Kp[o4 + c * 2 + 1];
            qb0[j] = Qp[o4 + c * 2]; qb1[j] = Qp[o4 + c * 2 + 1];
            vb[j]  = Vp[(size_t)tn * EE];
            abb[j] = ABp[(size_t)tn * HH];

            float pk  = ck0.x * s0.x,  pk2 = ck0.y * s0.y;
            float pq  = cq0.x * s0.x,  pq2 = cq0.y * s0.y;
            float kq  = ck0.x * cq0.x, kq2 = ck0.y * cq0.y;
            pk  = fmaf(ck0.z, s0.z, pk);   pk2 = fmaf(ck0.w, s0.w, pk2);
            pq  = fmaf(cq0.z, s0.z, pq);   pq2 = fmaf(cq0.w, s0.w, pq2);
            kq  = fmaf(ck0.z, cq0.z, kq);  kq2 = fmaf(ck0.w, cq0.w, kq2);
            pk  = fmaf(ck1.x, s1.x, pk);   pk2 = fmaf(ck1.y, s1.y, pk2);
            pq  = fmaf(cq1.x, s1.x, pq);   pq2 = fmaf(cq1.y, s1.y, pq2);
            kq  = fmaf(ck1.x, cq1.x, kq);  kq2 = fmaf(ck1.y, cq1.y, kq2);
            pk  = fmaf(ck1.z, s1.z, pk);   pk2 = fmaf(ck1.w, s1.w, pk2);
            pq  = fmaf(cq1.z, s1.z, pq);   pq2 = fmaf(cq1.w, s1.w, pq2);
            kq  = fmaf(ck1.z, cq1.z, kq);  kq2 = fmaf(ck1.w, cq1.w, kq2);
            pk += pk2; pq += pq2; kq += kq2;

            pk += __shfl_xor_sync(0xffffffffu, pk, 1);
            pq += __shfl_xor_sync(0xffffffffu, pq, 1);
            kq += __shfl_xor_sync(0xffffffffu, kq, 1);
            pk += __shfl_xor_sync(0xffffffffu, pk, 2);
            pq += __shfl_xor_sync(0xffffffffu, pq, 2);
            kq += __shfl_xor_sync(0xffffffffu, kq, 2);
            pk += __shfl_xor_sync(0xffffffffu, pk, 4);
            pq += __shfl_xor_sync(0xffffffffu, pq, 4);
            kq += __shfl_xor_sync(0xffffffffu, kq, 4);

            float delta = cbe * fmaf(-ca, pk, cv);
            float o = fmaf(ca, pq, delta * kq);
            if (c == 0) Op[(size_t)(t + j) * EE] = o;

            s0.x = fmaf(ca, s0.x, delta * ck0.x);
            s0.y = fmaf(ca, s0.y, delta * ck0.y);
            s0.z = fmaf(ca, s0.z, delta * ck0.z);
            s0.w = fmaf(ca, s0.w, delta * ck0.w);
            s1.x = fmaf(ca, s1.x, delta * ck1.x);
            s1.y = fmaf(ca, s1.y, delta * ck1.y);
            s1.z = fmaf(ca, s1.z, delta * ck1.z);
            s1.w = fmaf(ca, s1.w, delta * ck1.w);
        }
    }
}

// =============================================================
// RMSNorm + rms_w + SiLU(gate), fused bf16 hi/lo split output
// =============================================================
__global__ void rms_gate_split(const float* __restrict__ O, const float* __restrict__ G,
                               const float* __restrict__ rmsw,
                               ushort_t* __restrict__ YH, ushort_t* __restrict__ YL) {
    int gw   = blockIdx.x * 8 + (threadIdx.x >> 5);
    int lane = threadIdx.x & 31;
    int row = gw >> 4, h = gw & 15;
    size_t base = (size_t)row * EE + h * DD;

    float2 ov = ((const float2*)(O + base))[lane];
    float ss = fmaf(ov.x, ov.x, ov.y * ov.y);
#pragma unroll
    for (int o = 16; o; o >>= 1) ss += __shfl_xor_sync(0xffffffffu, ss, o);
    float scale = 1.f / sqrtf(ss * (1.f / 64.f) + 1e-6f);

    float2 gv = ((const float2*)(G + base))[lane];
    float gx = gv.x / (1.f + expf(-gv.x));
    float gy = gv.y / (1.f + expf(-gv.y));
    float2 rw = ((const float2*)rmsw)[lane];

    float yx = ov.x * scale * rw.x * gx;
    float yy = ov.y * scale * rw.y * gy;

    bf16 hx = __float2bfloat16(yx);
    bf16 hy = __float2bfloat16(yy);
    bf16 lx = __float2bfloat16(yx - __bfloat162float(hx));
    bf16 ly = __float2bfloat16(yy - __bfloat162float(hy));
    ushort_t hp[2] = { *(ushort_t*)&hx, *(ushort_t*)&hy };
    ushort_t lp[2] = { *(ushort_t*)&lx, *(ushort_t*)&ly };
    ((uint32_t*)(YH + base))[lane] = *(uint32_t*)hp;
    ((uint32_t*)(YL + base))[lane] = *(uint32_t*)lp;
}

// =============================================================
extern "C" void kernel_launch(void* const* d_in, const int* in_sizes, int n_in,
                              void* d_out, int out_size) {
    const float* x     = (const float*)d_in[0];
    const float* Wq    = (const float*)d_in[1];
    const float* Wk    = (const float*)d_in[2];
    const float* Wv    = (const float*)d_in[3];
    const float* Wa    = (const float*)d_in[4];
    const float* Wb    = (const float*)d_in[5];
    const float* Alog  = (const float*)d_in[6];
    const float* dtb   = (const float*)d_in[7];
    const float* Wg    = (const float*)d_in[8];
    const float* Wout  = (const float*)d_in[9];
    const float* rmsw  = (const float*)d_in[10];

    float *bq, *bk, *bv, *bg, *bo;
    float2* ab;
    ushort_t *xh, *xl, *yh, *yl;
    ushort_t *wqh, *wql, *wkh, *wkl, *wvh, *wvl, *wgh, *wgl, *woh, *wol;
    cudaGetSymbolAddress((void**)&bq, g_bq);
    cudaGetSymbolAddress((void**)&bk, g_bk);
    cudaGetSymbolAddress((void**)&bv, g_bv);
    cudaGetSymbolAddress((void**)&bg, g_bg);
    cudaGetSymbolAddress((void**)&bo, g_bo);
    cudaGetSymbolAddress((void**)&ab, g_ab);
    cudaGetSymbolAddress((void**)&xh, g_xh);
    cudaGetSymbolAddress((void**)&xl, g_xl);
    cudaGetSymbolAddress((void**)&yh, g_yh);
    cudaGetSymbolAddress((void**)&yl, g_yl);
    cudaGetSymbolAddress((void**)&wqh, g_wq_h); cudaGetSymbolAddress((void**)&wql, g_wq_l);
    cudaGetSymbolAddress((void**)&wkh, g_wk_h); cudaGetSymbolAddress((void**)&wkl, g_wk_l);
    cudaGetSymbolAddress((void**)&wvh, g_wv_h); cudaGetSymbolAddress((void**)&wvl, g_wv_l);
    cudaGetSymbolAddress((void**)&wgh, g_wg_h); cudaGetSymbolAddress((void**)&wgl, g_wg_l);
    cudaGetSymbolAddress((void**)&woh, g_wo_h); cudaGetSymbolAddress((void**)&wol, g_wo_l);

    dim3 tgrid(32, 32), tblk(256);
    split_f32<<<ROWS * EE / 1024, 256>>>(x, xh, xl);
    tsplit<<<tgrid, tblk>>>(Wq, wqh, wql);
    tsplit<<<tgrid, tblk>>>(Wk, wkh, wkl);
    tsplit<<<tgrid, tblk>>>(Wv, wvh, wvl);
    tsplit<<<tgrid, tblk>>>(Wg, wgh, wgl);
    tsplit<<<tgrid, tblk>>>(Wout, woh, wol);

    dim3 gg(EE / 64, ROWS / 128);   // (16, 64)
    gemm_mma<<<gg, 256>>>(xh, xl, wqh, wql, bq);
    gemm_mma<<<gg, 256>>>(xh, xl, wkh, wkl, bk);
    gemm_mma<<<gg, 256>>>(xh, xl, wvh, wvl, bv);
    gemm_mma<<<gg, 256>>>(xh, xl, wgh, wgl, bg);

    ab_kernel<<<ROWS / 8, 256>>>(x, Wa, Wb, Alog, dtb, ab);
    norm_qk<<<ROWS * HH / 8, 256>>>(bq, bk);

    scan_kernel<<<dim3(4, BB * HH), 128>>>(bq, bk, bv, ab, bo);

    rms_gate_split<<<ROWS * HH / 8, 256>>>(bo, bg, rmsw, yh, yl);

    gemm_mma<<<gg, 256>>>(yh, yl, woh, wol, (float*)d_out);
}